// round 13
// baseline (speedup 1.0000x reference)
#include <cuda_runtime.h>
#include <cstdint>

// Submanifold sparse conv — compacted per-offset gather-GEMM, atomic-free.
//  zero_kernel   : reset per-k counters
//  fused_kernel  : blocks [0,CEN_BLOCKS) -> center GEMM (out = bias + F@W13);
//                  rest -> compaction building per-k lists + inverse table.
//  taps_kernel   : scratch[(k,pos)] = F[nb] @ W[k]  (plain STG, no atomics)
//  reduce_kernel : out[site] += sum of this site's scratch rows (sole writer)

#define C 32
#define KTAPS 27
#define KCENTER 13
#define NCAP 16384                      // per-k list capacity (max cnt ~9.5k)

__device__ int   g_count[KTAPS];
__device__ int2  g_list[KTAPS * NCAP];
__device__ int   g_inv[2700000];        // [site*27+k] -> pos in k-list
__device__ float g_scratch[(size_t)KTAPS * NCAP * C];   // 56.6 MB tap results

typedef unsigned long long u64;

__device__ __forceinline__ u64 fma_f32x2(u64 a, u64 b, u64 c)
{
    u64 d;
    asm("fma.rn.f32x2 %0, %1, %2, %3;" : "=l"(d) : "l"(a), "l"(b), "l"(c));
    return d;
}
__device__ __forceinline__ u64 pack_f32x2(float lo, float hi)
{
    u64 d;
    asm("mov.b64 %0, {%1, %2};" : "=l"(d) : "f"(lo), "f"(hi));
    return d;
}
__device__ __forceinline__ float sum_f32x2(u64 v)
{
    float lo, hi;
    asm("mov.b64 {%0, %1}, %2;" : "=f"(lo), "=f"(hi) : "l"(v));
    return lo + hi;
}

// ---------------------------------------------------------------- zero
__global__ void zero_kernel()
{
    if (threadIdx.x < KTAPS) g_count[threadIdx.x] = 0;
}

// ---------------------------------------------------------------- fused center + compact
#define FB_THREADS 256
#define CEN_BLOCKS 592
#define CB_EPT 8
#define CB_ELEMS (FB_THREADS * CB_EPT)

__global__ void __launch_bounds__(FB_THREADS)
fused_kernel(const float* __restrict__ features,
             const float* __restrict__ weight,
             const float* __restrict__ bias,
             const int*   __restrict__ nbr_idx,
             const int*   __restrict__ nbr_mask,
             float* __restrict__ out,
             int n_sites, int n_elems)
{
    __shared__ union {
        struct { int scount[KTAPS]; int sbase[KTAPS]; } cp;
        float rows[FB_THREADS / 32][C];
    } sm;

    const int tid  = threadIdx.x;
    const int lane = tid & 31;
    const int wib  = tid >> 5;

    if (blockIdx.x < CEN_BLOCKS) {
        // ---------------- center GEMM ----------------
        u64 w2[C / 2];
        const float* w13 = weight + KCENTER * C * C;
        #pragma unroll
        for (int g = 0; g < C / 2; ++g)
            w2[g] = pack_f32x2(w13[(2 * g) * C + lane], w13[(2 * g + 1) * C + lane]);

        const float my_bias = bias[lane];
        float* row = sm.rows[wib];

        const int gwarp  = blockIdx.x * (FB_THREADS / 32) + wib;
        const int nwarps = CEN_BLOCKS * (FB_THREADS / 32);

        float fvA = 0.f;
        if (gwarp < n_sites) fvA = features[gwarp * C + lane];

        for (int site = gwarp; site < n_sites; site += nwarps) {
            const int nsite = site + nwarps;
            float fvB = 0.f;
            if (nsite < n_sites) fvB = features[nsite * C + lane];

            row[lane] = fvA;
            __syncwarp();

            u64 ta = 0ull, tb = 0ull;
            #pragma unroll
            for (int g = 0; g < 8; ++g) {
                const ulonglong2 fp = *reinterpret_cast<const ulonglong2*>(row + (g << 2));
                ta = fma_f32x2(fp.x, w2[2 * g + 0], ta);
                tb = fma_f32x2(fp.y, w2[2 * g + 1], tb);
            }
            __syncwarp();

            out[site * C + lane] = my_bias + sum_f32x2(ta) + sum_f32x2(tb);
            fvA = fvB;
        }
    } else {
        // ---------------- compaction (coalesced) ----------------
        if (tid < KTAPS) sm.cp.scount[tid] = 0;
        __syncthreads();

        const int base = (blockIdx.x - CEN_BLOCKS) * CB_ELEMS;
        bool act[CB_EPT];

        #pragma unroll
        for (int s = 0; s < CB_EPT; ++s) {
            const int e = base + s * FB_THREADS + tid;
            bool a = false;
            if (e < n_elems) {
                const int k = e % KTAPS;
                a = (k != KCENTER) && (nbr_mask[e] != 0);
                if (a) atomicAdd(&sm.cp.scount[k], 1);
            }
            act[s] = a;
        }
        __syncthreads();

        if (tid < KTAPS) {
            const int c = sm.cp.scount[tid];
            sm.cp.sbase[tid]  = c ? atomicAdd(&g_count[tid], c) : 0;
            sm.cp.scount[tid] = 0;
        }
        __syncthreads();

        #pragma unroll
        for (int s = 0; s < CB_EPT; ++s) {
            if (act[s]) {
                const int e    = base + s * FB_THREADS + tid;
                const int site = e / KTAPS;
                const int k    = e - site * KTAPS;
                const int pos  = sm.cp.sbase[k] + atomicAdd(&sm.cp.scount[k], 1);
                g_list[k * NCAP + pos] = make_int2(site, nbr_idx[e]);
                g_inv[e] = pos;
            }
        }
    }
}

// ---------------------------------------------------------------- taps
#define PB_WARPS 8
#define PB_THREADS 256
#define PB_BLOCKS_X 17      // 26*17 = 442 blocks ~= one wave at 3 blocks/SM

__global__ void __launch_bounds__(PB_THREADS, 3)
taps_kernel(const float* __restrict__ features,
            const float* __restrict__ weight)
{
    __shared__ float rows[PB_WARPS][8][C];

    int k = blockIdx.y;
    if (k >= KCENTER) ++k;

    const int tid  = threadIdx.x;
    const int lane = tid & 31;
    const int wib  = tid >> 5;

    u64 w2[C / 2];
    const float* wkp = weight + k * C * C;
    #pragma unroll
    for (int g = 0; g < C / 2; ++g)
        w2[g] = pack_f32x2(wkp[(2 * g) * C + lane], wkp[(2 * g + 1) * C + lane]);

    const int cnt    = g_count[k];
    const int nquads = cnt >> 2;
    const int warps_per_k = gridDim.x * PB_WARPS;
    const int wid_in_k = blockIdx.x * PB_WARPS + wib;
    const int chunk = (nquads + warps_per_k - 1) / warps_per_k;
    int q = wid_in_k * chunk;
    const int qend = min(q + chunk, nquads);

    const int4* list4 = reinterpret_cast<const int4*>(g_list + k * NCAP);
    float* kscratch = g_scratch + (size_t)k * NCAP * C;
    float (*myrows)[C] = rows[wib];

    if (q < qend) {
        int4 a0 = list4[2 * q], a1 = list4[2 * q + 1];
        int4 b0 = a0, b1 = a1;
        if (q + 1 < qend) { b0 = list4[2 * q + 2]; b1 = list4[2 * q + 3]; }
        float fA0 = features[a0.y * C + lane];
        float fA1 = features[a0.w * C + lane];
        float fA2 = features[a1.y * C + lane];
        float fA3 = features[a1.w * C + lane];

        for (;;) {
            const bool hasB = (q + 1 < qend);

            int4 c0 = a0, c1 = a1;
            if (q + 2 < qend) { c0 = list4[2 * q + 4]; c1 = list4[2 * q + 5]; }
            float fB0 = 0.f, fB1 = 0.f, fB2 = 0.f, fB3 = 0.f;
            if (hasB) {
                fB0 = features[b0.y * C + lane];
                fB1 = features[b0.w * C + lane];
                fB2 = features[b1.y * C + lane];
                fB3 = features[b1.w * C + lane];
            }

            const int buf = (q & 1) << 2;
            myrows[buf + 0][lane] = fA0;
            myrows[buf + 1][lane] = fA1;
            myrows[buf + 2][lane] = fA2;
            myrows[buf + 3][lane] = fA3;
            __syncwarp();

            u64 t0 = 0ull, t1 = 0ull, t2 = 0ull, t3 = 0ull;
            #pragma unroll
            for (int g = 0; g < 8; ++g) {
                const ulonglong2 f0 = *reinterpret_cast<const ulonglong2*>(myrows[buf + 0] + (g << 2));
                const ulonglong2 f1 = *reinterpret_cast<const ulonglong2*>(myrows[buf + 1] + (g << 2));
                const ulonglong2 f2 = *reinterpret_cast<const ulonglong2*>(myrows[buf + 2] + (g << 2));
                const ulonglong2 f3 = *reinterpret_cast<const ulonglong2*>(myrows[buf + 3] + (g << 2));
                const u64 wa = w2[2 * g + 0];
                const u64 wb = w2[2 * g + 1];
                t0 = fma_f32x2(f0.x, wa, t0); t0 = fma_f32x2(f0.y, wb, t0);
                t1 = fma_f32x2(f1.x, wa, t1); t1 = fma_f32x2(f1.y, wb, t1);
                t2 = fma_f32x2(f2.x, wa, t2); t2 = fma_f32x2(f2.y, wb, t2);
                t3 = fma_f32x2(f3.x, wa, t3); t3 = fma_f32x2(f3.y, wb, t3);
            }

            // plain coalesced stores — no atomics
            const int p4 = q << 2;
            kscratch[(p4 + 0) * C + lane] = sum_f32x2(t0);
            kscratch[(p4 + 1) * C + lane] = sum_f32x2(t1);
            kscratch[(p4 + 2) * C + lane] = sum_f32x2(t2);
            kscratch[(p4 + 3) * C + lane] = sum_f32x2(t3);

            if (!hasB) break;
            ++q;
            a0 = b0; a1 = b1; b0 = c0; b1 = c1;
            fA0 = fB0; fA1 = fB1; fA2 = fB2; fA3 = fB3;
        }
    }

    // ---- tail (cnt & 3 taps), handled by warp 0 of this k ----
    if (wid_in_k == 0) {
        const int2* list = g_list + k * NCAP;
        for (int t = nquads << 2; t < cnt; ++t) {
            const int2 ent = list[t];
            const float fv = features[ent.y * C + lane];
            myrows[0][lane] = fv;
            __syncwarp();
            u64 acc = 0ull;
            #pragma unroll
            for (int g = 0; g < 8; ++g) {
                const ulonglong2 f = *reinterpret_cast<const ulonglong2*>(myrows[0] + (g << 2));
                acc = fma_f32x2(f.x, w2[2 * g + 0], acc);
                acc = fma_f32x2(f.y, w2[2 * g + 1], acc);
            }
            __syncwarp();
            kscratch[t * C + lane] = sum_f32x2(acc);
        }
    }
}

// ---------------------------------------------------------------- reduce
#define RD_WARPS 8
#define RD_THREADS 256
#define RD_BLOCKS 296

__global__ void __launch_bounds__(RD_THREADS)
reduce_kernel(const int* __restrict__ nbr_mask,
              float* __restrict__ out,
              int n_sites)
{
    const int tid  = threadIdx.x;
    const int lane = tid & 31;
    const int wib  = tid >> 5;

    const int gwarp  = blockIdx.x * RD_WARPS + wib;
    const int nwarps = RD_BLOCKS * RD_WARPS;

    // prime first site's header
    int mA = 0, iA = 0;
    if (gwarp < n_sites && lane < KTAPS) {
        mA = nbr_mask[gwarp * KTAPS + lane];
        iA = g_inv[gwarp * KTAPS + lane];
    }

    for (int site = gwarp; site < n_sites; site += nwarps) {
        // prefetch next site's header
        const int nsite = site + nwarps;
        int mB = 0, iB = 0;
        if (nsite < n_sites && lane < KTAPS) {
            mB = nbr_mask[nsite * KTAPS + lane];
            iB = g_inv[nsite * KTAPS + lane];
        }

        unsigned bits = __ballot_sync(0xffffffffu, mA != 0 && lane < KTAPS);
        bits &= ~(1u << KCENTER);

        if (bits) {
            float acc = out[site * C + lane];    // bias + center from fused
            while (bits) {
                const int k = __ffs(bits) - 1;
                bits &= bits - 1;
                const int pos = __shfl_sync(0xffffffffu, iA, k);
                acc += g_scratch[((size_t)k * NCAP + pos) * C + lane];
            }
            out[site * C + lane] = acc;
        }

        mA = mB;
        iA = iB;
    }
}

// ---------------------------------------------------------------- launch
extern "C" void kernel_launch(void* const* d_in, const int* in_sizes, int n_in,
                              void* d_out, int out_size)
{
    const float* features = (const float*)d_in[0];
    const float* weight   = (const float*)d_in[1];
    const float* bias     = (const float*)d_in[2];
    const int*   nbr_idx  = (const int*)d_in[3];
    const int*   nbr_mask = (const int*)d_in[4];
    float*       out      = (float*)d_out;

    const int n_sites = in_sizes[0] / C;
    const int n_elems = n_sites * KTAPS;

    zero_kernel<<<1, 32>>>();

    const int cblocks = (n_elems + CB_ELEMS - 1) / CB_ELEMS;
    fused_kernel<<<CEN_BLOCKS + cblocks, FB_THREADS>>>(
        features, weight, bias, nbr_idx, nbr_mask, out, n_sites, n_elems);

    dim3 tgrid(PB_BLOCKS_X, KTAPS - 1);
    taps_kernel<<<tgrid, PB_THREADS>>>(features, weight);

    reduce_kernel<<<RD_BLOCKS, RD_THREADS>>>(nbr_mask, out, n_sites);
}

// round 14
// speedup vs baseline: 2.9552x; 2.9552x over previous
#include <cuda_runtime.h>
#include <cstdint>

// Submanifold sparse conv — compacted per-offset gather-GEMM.
//  zero_kernel   : reset per-k counters
//  fused_kernel  : blocks [0,CEN_BLOCKS) -> center GEMM (out = bias + F@W13);
//                  rest -> element-parallel compaction.
//  taps_kernel   : out[site] += F[nb] @ W[k]; W[k] packed in b64 regs;
//                  cp.async feature pipeline 4 quads (16 taps) deep,
//                  coalesced per-lane atomicAdd epilogue.

#define C 32
#define KTAPS 27
#define KCENTER 13
#define NCAP 131072

__device__ int  g_count[KTAPS];
__device__ int2 g_list[KTAPS * NCAP];

typedef unsigned long long u64;

__device__ __forceinline__ u64 fma_f32x2(u64 a, u64 b, u64 c)
{
    u64 d;
    asm("fma.rn.f32x2 %0, %1, %2, %3;" : "=l"(d) : "l"(a), "l"(b), "l"(c));
    return d;
}
__device__ __forceinline__ u64 pack_f32x2(float lo, float hi)
{
    u64 d;
    asm("mov.b64 %0, {%1, %2};" : "=l"(d) : "f"(lo), "f"(hi));
    return d;
}
__device__ __forceinline__ float sum_f32x2(u64 v)
{
    float lo, hi;
    asm("mov.b64 {%0, %1}, %2;" : "=f"(lo), "=f"(hi) : "l"(v));
    return lo + hi;
}
__device__ __forceinline__ void cp_async4(uint32_t saddr, const float* gptr)
{
    asm volatile("cp.async.ca.shared.global [%0], [%1], 4;"
                 :: "r"(saddr), "l"(gptr) : "memory");
}
__device__ __forceinline__ void cp_commit()
{
    asm volatile("cp.async.commit_group;" ::: "memory");
}
template <int N>
__device__ __forceinline__ void cp_wait()
{
    asm volatile("cp.async.wait_group %0;" :: "n"(N) : "memory");
}

// ---------------------------------------------------------------- zero
__global__ void zero_kernel()
{
    if (threadIdx.x < KTAPS) g_count[threadIdx.x] = 0;
}

// ---------------------------------------------------------------- fused center + compact
#define FB_THREADS 256
#define CEN_BLOCKS 592
#define CB_EPT 8
#define CB_ELEMS (FB_THREADS * CB_EPT)

__global__ void __launch_bounds__(FB_THREADS)
fused_kernel(const float* __restrict__ features,
             const float* __restrict__ weight,
             const float* __restrict__ bias,
             const int*   __restrict__ nbr_idx,
             const int*   __restrict__ nbr_mask,
             float* __restrict__ out,
             int n_sites, int n_elems)
{
    __shared__ union {
        struct { int scount[KTAPS]; int sbase[KTAPS]; } cp;
        float rows[FB_THREADS / 32][C];
    } sm;

    const int tid  = threadIdx.x;
    const int lane = tid & 31;
    const int wib  = tid >> 5;

    if (blockIdx.x < CEN_BLOCKS) {
        // ---------------- center GEMM ----------------
        u64 w2[C / 2];
        const float* w13 = weight + KCENTER * C * C;
        #pragma unroll
        for (int g = 0; g < C / 2; ++g)
            w2[g] = pack_f32x2(w13[(2 * g) * C + lane], w13[(2 * g + 1) * C + lane]);

        const float my_bias = bias[lane];
        float* row = sm.rows[wib];

        const int gwarp  = blockIdx.x * (FB_THREADS / 32) + wib;
        const int nwarps = CEN_BLOCKS * (FB_THREADS / 32);

        float fvA = 0.f;
        if (gwarp < n_sites) fvA = features[gwarp * C + lane];

        for (int site = gwarp; site < n_sites; site += nwarps) {
            const int nsite = site + nwarps;
            float fvB = 0.f;
            if (nsite < n_sites) fvB = features[nsite * C + lane];

            row[lane] = fvA;
            __syncwarp();

            u64 ta = 0ull, tb = 0ull;
            #pragma unroll
            for (int g = 0; g < 8; ++g) {
                const ulonglong2 fp = *reinterpret_cast<const ulonglong2*>(row + (g << 2));
                ta = fma_f32x2(fp.x, w2[2 * g + 0], ta);
                tb = fma_f32x2(fp.y, w2[2 * g + 1], tb);
            }
            __syncwarp();

            out[site * C + lane] = my_bias + sum_f32x2(ta) + sum_f32x2(tb);
            fvA = fvB;
        }
    } else {
        // ---------------- compaction (coalesced) ----------------
        if (tid < KTAPS) sm.cp.scount[tid] = 0;
        __syncthreads();

        const int base = (blockIdx.x - CEN_BLOCKS) * CB_ELEMS;
        bool act[CB_EPT];

        #pragma unroll
        for (int s = 0; s < CB_EPT; ++s) {
            const int e = base + s * FB_THREADS + tid;
            bool a = false;
            if (e < n_elems) {
                const int k = e % KTAPS;
                a = (k != KCENTER) && (nbr_mask[e] != 0);
                if (a) atomicAdd(&sm.cp.scount[k], 1);
            }
            act[s] = a;
        }
        __syncthreads();

        if (tid < KTAPS) {
            const int c = sm.cp.scount[tid];
            sm.cp.sbase[tid]  = c ? atomicAdd(&g_count[tid], c) : 0;
            sm.cp.scount[tid] = 0;
        }
        __syncthreads();

        #pragma unroll
        for (int s = 0; s < CB_EPT; ++s) {
            if (act[s]) {
                const int e    = base + s * FB_THREADS + tid;
                const int site = e / KTAPS;
                const int k    = e - site * KTAPS;
                const int pos  = sm.cp.sbase[k] + atomicAdd(&sm.cp.scount[k], 1);
                g_list[k * NCAP + pos] = make_int2(site, nbr_idx[e]);
            }
        }
    }
}

// ---------------------------------------------------------------- taps
#define PB_WARPS 8
#define PB_THREADS 256
#define PB_BLOCKS_X 17      // 26*17 = 442 blocks ~= one wave at 3 blocks/SM
#define DEPTH 4             // quads in flight (16 taps)

__global__ void __launch_bounds__(PB_THREADS, 3)
taps_kernel(const float* __restrict__ features,
            const float* __restrict__ weight,
            float* __restrict__ out)
{
    __shared__ float rows[PB_WARPS][DEPTH * 4][C];   // 16 KB
    __shared__ int   ssite[PB_WARPS][DEPTH * 4];

    int k = blockIdx.y;
    if (k >= KCENTER) ++k;

    const int tid  = threadIdx.x;
    const int lane = tid & 31;
    const int wib  = tid >> 5;

    u64 w2[C / 2];
    const float* wkp = weight + k * C * C;
    #pragma unroll
    for (int g = 0; g < C / 2; ++g)
        w2[g] = pack_f32x2(wkp[(2 * g) * C + lane], wkp[(2 * g + 1) * C + lane]);

    const int cnt    = g_count[k];
    const int nquads = cnt >> 2;
    const int warps_per_k = gridDim.x * PB_WARPS;
    const int wid_in_k = blockIdx.x * PB_WARPS + wib;
    const int chunk = (nquads + warps_per_k - 1) / warps_per_k;
    const int q0   = wid_in_k * chunk;
    const int qend = min(q0 + chunk, nquads);

    const int4* list4 = reinterpret_cast<const int4*>(g_list + k * NCAP);
    const uint32_t rowbase =
        (uint32_t)__cvta_generic_to_shared(&rows[wib][0][0]);

    // issue gathers for one quad into phase ph
    auto issue_quad = [&](int4 e0, int4 e1, int ph) {
        const uint32_t d = rowbase + (((ph << 2) * C) + lane) * 4u;
        cp_async4(d + 0 * C * 4u, features + (size_t)e0.y * C + lane);
        cp_async4(d + 1 * C * 4u, features + (size_t)e0.w * C + lane);
        cp_async4(d + 2 * C * 4u, features + (size_t)e1.y * C + lane);
        cp_async4(d + 3 * C * 4u, features + (size_t)e1.w * C + lane);
        if (lane == 0) {
            ssite[wib][(ph << 2) + 0] = e0.x;
            ssite[wib][(ph << 2) + 1] = e0.z;
            ssite[wib][(ph << 2) + 2] = e1.x;
            ssite[wib][(ph << 2) + 3] = e1.z;
        }
        cp_commit();
    };

    if (q0 < qend) {
        // ---- prologue: fill DEPTH pipeline stages (empty groups pad) ----
        #pragma unroll
        for (int p = 0; p < DEPTH; ++p) {
            if (q0 + p < qend)
                issue_quad(list4[2 * (q0 + p)], list4[2 * (q0 + p) + 1], p);
            else
                cp_commit();
        }

        // entries for quad q0+DEPTH, prefetched one iteration ahead
        int4 en0 = make_int4(0, 0, 0, 0), en1 = en0;
        if (q0 + DEPTH < qend) {
            en0 = list4[2 * (q0 + DEPTH)];
            en1 = list4[2 * (q0 + DEPTH) + 1];
        }

        for (int q = q0; q < qend; ++q) {
            const int ph = (q - q0) & (DEPTH - 1);

            cp_wait<DEPTH - 1>();       // oldest quad (q) resident
            __syncwarp();

            const float* r0 = rows[wib][(ph << 2) + 0];
            const float* r1 = rows[wib][(ph << 2) + 1];
            const float* r2 = rows[wib][(ph << 2) + 2];
            const float* r3 = rows[wib][(ph << 2) + 3];

            u64 t0 = 0ull, t1 = 0ull, t2 = 0ull, t3 = 0ull;
            #pragma unroll
            for (int g = 0; g < 8; ++g) {
                const ulonglong2 f0 = *reinterpret_cast<const ulonglong2*>(r0 + (g << 2));
                const ulonglong2 f1 = *reinterpret_cast<const ulonglong2*>(r1 + (g << 2));
                const ulonglong2 f2 = *reinterpret_cast<const ulonglong2*>(r2 + (g << 2));
                const ulonglong2 f3 = *reinterpret_cast<const ulonglong2*>(r3 + (g << 2));
                const u64 wa = w2[2 * g + 0];
                const u64 wb = w2[2 * g + 1];
                t0 = fma_f32x2(f0.x, wa, t0); t0 = fma_f32x2(f0.y, wb, t0);
                t1 = fma_f32x2(f1.x, wa, t1); t1 = fma_f32x2(f1.y, wb, t1);
                t2 = fma_f32x2(f2.x, wa, t2); t2 = fma_f32x2(f2.y, wb, t2);
                t3 = fma_f32x2(f3.x, wa, t3); t3 = fma_f32x2(f3.y, wb, t3);
            }

            const int s0 = ssite[wib][(ph << 2) + 0];
            const int s1 = ssite[wib][(ph << 2) + 1];
            const int s2 = ssite[wib][(ph << 2) + 2];
            const int s3 = ssite[wib][(ph << 2) + 3];

            atomicAdd(&out[s0 * C + lane], sum_f32x2(t0));
            atomicAdd(&out[s1 * C + lane], sum_f32x2(t1));
            atomicAdd(&out[s2 * C + lane], sum_f32x2(t2));
            atomicAdd(&out[s3 * C + lane], sum_f32x2(t3));

            __syncwarp();               // all lanes done reading phase ph rows

            const int nx = q + DEPTH;
            if (nx < qend) issue_quad(en0, en1, ph);
            else           cp_commit();

            if (nx + 1 < qend) {
                en0 = list4[2 * (nx + 1)];
                en1 = list4[2 * (nx + 1) + 1];
            }
        }

        cp_wait<0>();                   // drain before tail reuses smem
        __syncwarp();
    }

    // ---- tail (cnt & 3 taps), handled by warp 0 of this k ----
    if (wid_in_k == 0) {
        const int2* list = g_list + k * NCAP;
        for (int t = nquads << 2; t < cnt; ++t) {
            const int2 ent = list[t];
            const float fv = features[(size_t)ent.y * C + lane];
            rows[wib][0][lane] = fv;
            __syncwarp();
            u64 acc = 0ull;
            #pragma unroll
            for (int g = 0; g < 8; ++g) {
                const ulonglong2 f = *reinterpret_cast<const ulonglong2*>(rows[wib][0] + (g << 2));
                acc = fma_f32x2(f.x, w2[2 * g + 0], acc);
                acc = fma_f32x2(f.y, w2[2 * g + 1], acc);
            }
            __syncwarp();
            atomicAdd(&out[ent.x * C + lane], sum_f32x2(acc));
        }
    }
}

// ---------------------------------------------------------------- launch
extern "C" void kernel_launch(void* const* d_in, const int* in_sizes, int n_in,
                              void* d_out, int out_size)
{
    const float* features = (const float*)d_in[0];
    const float* weight   = (const float*)d_in[1];
    const float* bias     = (const float*)d_in[2];
    const int*   nbr_idx  = (const int*)d_in[3];
    const int*   nbr_mask = (const int*)d_in[4];
    float*       out      = (float*)d_out;

    const int n_sites = in_sizes[0] / C;
    const int n_elems = n_sites * KTAPS;

    zero_kernel<<<1, 32>>>();

    const int cblocks = (n_elems + CB_ELEMS - 1) / CB_ELEMS;
    fused_kernel<<<CEN_BLOCKS + cblocks, FB_THREADS>>>(
        features, weight, bias, nbr_idx, nbr_mask, out, n_sites, n_elems);

    dim3 tgrid(PB_BLOCKS_X, KTAPS - 1);
    taps_kernel<<<tgrid, PB_THREADS>>>(features, weight, out);
}